// round 1
// baseline (speedup 1.0000x reference)
#include <cuda_runtime.h>
#include <cuda_bf16.h>

// ============================================================================
// LRML scoring, restructured:
//   logits[b,n,m] = sum_d item[n,d] * (u[b,d]*K[d,m])       -> GEMM vs W
//   u.item[b,n]   = sum_d item[n,d] * u[b,d]                -> extra W column
//   IM[n,m]       = sum_d item[n,d] * mem[m,d]              -> extra W columns
//   score^2 = |u|^2 + |item|^2 - 2 u.item
//             + 2*att.(UM - IM) + att^T G att,   G = mem mem^T, UM = u mem^T
// ============================================================================

#define D_DIM   128
#define M_DIM   20
#define B_USERS 16
#define N_MAX   50000
#define C_USE   356            // 16*21 + 20 useful columns
#define C_PAD   384            // padded to 12 warps
#define GEMM_NT 384
#define IT      6              // items per block iteration
#define GEMM_GRID 148

// Scratch (device globals: allocation-free rule)
__device__ float g_W[64 * C_PAD * 2];          // [d2][c] as f32x2
__device__ float g_logits[(size_t)N_MAX * C_PAD];
__device__ float g_it2[N_MAX];
__device__ float g_UM[B_USERS * M_DIM];
__device__ float g_u2[B_USERS];
__device__ float g_G[M_DIM * M_DIM];

__device__ __forceinline__ float2 ffma2(float2 a, float2 b, float2 c) {
    unsigned long long ra = *reinterpret_cast<unsigned long long*>(&a);
    unsigned long long rb = *reinterpret_cast<unsigned long long*>(&b);
    unsigned long long rc = *reinterpret_cast<unsigned long long*>(&c);
    unsigned long long rd;
    asm("fma.rn.f32x2 %0, %1, %2, %3;" : "=l"(rd) : "l"(ra), "l"(rb), "l"(rc));
    return *reinterpret_cast<float2*>(&rd);
}

// ----------------------------------------------------------------------------
// Precompute: W, UM, u2, G.  One block.
// ----------------------------------------------------------------------------
__global__ void pre_kernel(const float* __restrict__ users,
                           const float* __restrict__ keyM,   // [D][M]
                           const float* __restrict__ mems,   // [M][D]
                           const void*  __restrict__ ids_raw)
{
    __shared__ int s_uid[B_USERS];
    const int tid = threadIdx.x;

    if (tid == 0) {
        // JAX without x64 silently downcasts int64 -> int32; sniff the layout.
        const long long* p64 = (const long long*)ids_raw;
        const int*       p32 = (const int*)ids_raw;
        bool is64 = true;
        for (int i = 0; i < 8; i++) {
            long long v = p64[i];
            if (v < 0 || v >= (1LL << 31)) is64 = false;
        }
        for (int i = 0; i < B_USERS; i++)
            s_uid[i] = is64 ? (int)p64[i] : p32[i];
    }
    __syncthreads();

    // W: [d2][c] pair-interleaved
    for (int idx = tid; idx < 64 * C_PAD; idx += blockDim.x) {
        int d2 = idx / C_PAD, c = idx % C_PAD;
        int d0 = 2 * d2, d1 = d0 + 1;
        float w0 = 0.f, w1 = 0.f;
        if (c < B_USERS * 21) {
            int b = c / 21, j = c % 21;
            int uid = s_uid[b];
            float ua = users[(size_t)uid * D_DIM + d0];
            float ub = users[(size_t)uid * D_DIM + d1];
            if (j < M_DIM) { w0 = ua * keyM[d0 * M_DIM + j]; w1 = ub * keyM[d1 * M_DIM + j]; }
            else           { w0 = ua;                        w1 = ub; }
        } else if (c < C_USE) {
            int m = c - B_USERS * 21;
            w0 = mems[m * D_DIM + d0];
            w1 = mems[m * D_DIM + d1];
        }
        g_W[2 * idx]     = w0;
        g_W[2 * idx + 1] = w1;
    }

    // UM[b][m] = u_b . mem_m
    for (int t = tid; t < B_USERS * M_DIM; t += blockDim.x) {
        int b = t / M_DIM, m = t % M_DIM;
        int uid = s_uid[b];
        float s = 0.f;
        for (int d = 0; d < D_DIM; d++)
            s += users[(size_t)uid * D_DIM + d] * mems[m * D_DIM + d];
        g_UM[t] = s;
    }

    // |u_b|^2
    for (int t = tid; t < B_USERS; t += blockDim.x) {
        int uid = s_uid[t];
        float s = 0.f;
        for (int d = 0; d < D_DIM; d++) {
            float v = users[(size_t)uid * D_DIM + d];
            s += v * v;
        }
        g_u2[t] = s;
    }

    // G[m][m'] = mem_m . mem_m'
    for (int t = tid; t < M_DIM * M_DIM; t += blockDim.x) {
        int m = t / M_DIM, mm = t % M_DIM;
        float s = 0.f;
        for (int d = 0; d < D_DIM; d++)
            s += mems[m * D_DIM + d] * mems[mm * D_DIM + d];
        g_G[t] = s;
    }
}

// ----------------------------------------------------------------------------
// GEMM: logits[n][c] = item[n] . W[:,c].   W resident in shared (192KB),
// thread-per-column, IT items staged per iteration, f32x2 FMAs.
// Also computes |item|^2 from the staged tile.
// ----------------------------------------------------------------------------
__global__ void __launch_bounds__(GEMM_NT, 1)
gemm_kernel(const float* __restrict__ items, int N)
{
    extern __shared__ float smem[];
    float2* Ws = (float2*)smem;                    // [64][C_PAD] f32x2
    float*  its = smem + 64 * C_PAD * 2;           // [IT][128]

    const int tid = threadIdx.x;
    const int c = tid;

    // Load W into shared once
    const float2* Wg2 = (const float2*)g_W;
    for (int i = tid; i < 64 * C_PAD; i += GEMM_NT)
        Ws[i] = Wg2[i];
    __syncthreads();

    const float4* itemsv = (const float4*)items;

    for (int base = blockIdx.x * IT; base < N; base += gridDim.x * IT) {
        // ---- stage IT items (float4 coalesced) ----
        for (int i = tid; i < IT * 32; i += GEMM_NT) {
            int it_i = i >> 5, off = i & 31;
            int n = base + it_i;
            float4 v = (n < N) ? itemsv[(size_t)n * 32 + off]
                               : make_float4(0.f, 0.f, 0.f, 0.f);
            ((float4*)its)[i] = v;
        }
        __syncthreads();

        // ---- main f32x2 accumulation ----
        float2 acc[IT];
#pragma unroll
        for (int i = 0; i < IT; i++) acc[i] = make_float2(0.f, 0.f);

        const float4* itp4 = (const float4*)its;   // [IT][32]
#pragma unroll 4
        for (int d2 = 0; d2 < 64; d2 += 4) {
            float2 w0 = Ws[(d2 + 0) * C_PAD + c];
            float2 w1 = Ws[(d2 + 1) * C_PAD + c];
            float2 w2 = Ws[(d2 + 2) * C_PAD + c];
            float2 w3 = Ws[(d2 + 3) * C_PAD + c];
#pragma unroll
            for (int i = 0; i < IT; i++) {
                float4 A = itp4[i * 32 + (d2 >> 1)];
                float4 Bv = itp4[i * 32 + (d2 >> 1) + 1];
                acc[i] = ffma2(w0, make_float2(A.x, A.y), acc[i]);
                acc[i] = ffma2(w1, make_float2(A.z, A.w), acc[i]);
                acc[i] = ffma2(w2, make_float2(Bv.x, Bv.y), acc[i]);
                acc[i] = ffma2(w3, make_float2(Bv.z, Bv.w), acc[i]);
            }
        }

        // ---- |item|^2 via first IT warps ----
        if (tid < IT * 32) {
            int i = tid >> 5, l = tid & 31;
            float4 v = ((const float4*)its)[i * 32 + l];
            float s = v.x * v.x + v.y * v.y + v.z * v.z + v.w * v.w;
#pragma unroll
            for (int o = 16; o; o >>= 1)
                s += __shfl_xor_sync(0xffffffffu, s, o);
            if (l == 0 && base + i < N) g_it2[base + i] = s;
        }
        __syncthreads();   // its fully consumed before next staging

        // ---- store logits (coalesced across c) ----
#pragma unroll
        for (int i = 0; i < IT; i++) {
            int n = base + i;
            if (n < N) g_logits[(size_t)n * C_PAD + c] = acc[i].x + acc[i].y;
        }
    }
}

// ----------------------------------------------------------------------------
// Epilogue: per (b,n): softmax over M, Gram quadratic form, distance.
// Thread mapping: b = idx & 15 (logits row shared by 16 threads of a warp).
// ----------------------------------------------------------------------------
__global__ void epi_kernel(float* __restrict__ out, int N)
{
    __shared__ float Gs[M_DIM * M_DIM];
    __shared__ float UMs[B_USERS * M_DIM];
    __shared__ float u2s[B_USERS];

    const int tid = threadIdx.x;
    for (int i = tid; i < M_DIM * M_DIM; i += blockDim.x) Gs[i] = g_G[i];
    for (int i = tid; i < B_USERS * M_DIM; i += blockDim.x) UMs[i] = g_UM[i];
    if (tid < B_USERS) u2s[tid] = g_u2[tid];
    __syncthreads();

    long long idx = (long long)blockIdx.x * blockDim.x + tid;
    if (idx >= (long long)B_USERS * N) return;
    int b = (int)(idx & (B_USERS - 1));
    int n = (int)(idx >> 4);

    const float* row = g_logits + (size_t)n * C_PAD;
    const float* lb = row + b * 21;

    float l[M_DIM];
#pragma unroll
    for (int j = 0; j < M_DIM; j++) l[j] = lb[j];
    float uit = lb[M_DIM];

    float mx = l[0];
#pragma unroll
    for (int j = 1; j < M_DIM; j++) mx = fmaxf(mx, l[j]);

    float e[M_DIM];
    float S = 0.f;
#pragma unroll
    for (int j = 0; j < M_DIM; j++) { e[j] = __expf(l[j] - mx); S += e[j]; }

    // att.(UM - IM) numerator
    float num1 = 0.f;
#pragma unroll
    for (int j = 0; j < M_DIM; j++)
        num1 += e[j] * (UMs[b * M_DIM + j] - row[B_USERS * 21 + j]);

    // att^T G att numerator
    float Q = 0.f;
#pragma unroll 4
    for (int m = 0; m < M_DIM; m++) {
        float gv = 0.f;
#pragma unroll
        for (int j = 0; j < M_DIM; j++)
            gv += Gs[m * M_DIM + j] * e[j];
        Q += e[m] * gv;
    }

    float invS = 1.f / S;
    float s2 = u2s[b] + g_it2[n] - 2.f * uit + 2.f * num1 * invS + Q * invS * invS;
    out[(size_t)b * N + n] = -sqrtf(fmaxf(s2, 0.f));
}

// ----------------------------------------------------------------------------
extern "C" void kernel_launch(void* const* d_in, const int* in_sizes, int n_in,
                              void* d_out, int out_size)
{
    const float* users = (const float*)d_in[0];
    const float* items = (const float*)d_in[1];
    const float* keyM  = (const float*)d_in[2];
    const float* mems  = (const float*)d_in[3];
    const void*  ids   = d_in[4];
    float* out = (float*)d_out;

    const int N = in_sizes[1] / D_DIM;

    const int smem_bytes = 64 * C_PAD * 8 + IT * D_DIM * 4;  // 196608 + 3072
    cudaFuncSetAttribute(gemm_kernel,
                         cudaFuncAttributeMaxDynamicSharedMemorySize, smem_bytes);

    pre_kernel<<<1, 512>>>(users, keyM, mems, ids);
    gemm_kernel<<<GEMM_GRID, GEMM_NT, smem_bytes>>>(items, N);

    long long total = (long long)B_USERS * N;
    int blocks = (int)((total + 255) / 256);
    epi_kernel<<<blocks, 256>>>(out, N);
}

// round 2
// speedup vs baseline: 2.4159x; 2.4159x over previous
#include <cuda_runtime.h>
#include <cuda_bf16.h>

// ============================================================================
// LRML scoring, restructured + tensor-core GEMM (tf32 mma.sync):
//   logits[n,c] = item[n,:] @ Wt[c,:]   for 384 columns:
//     c in [0,336): b*21+m -> u_b[d]*K[d,m];  b*21+20 -> u_b[d] (u.item)
//     c in [336,356): mem_m[d]                (IM columns)
//   score^2 = |u|^2 + |item|^2 - 2 u.item + 2 att.(UM - IM) + att^T G att
// ============================================================================

#define D_DIM   128
#define M_DIM   20
#define B_USERS 16
#define N_MAX   50000
#define C_USE   356
#define C_PAD   384
#define CHUNK   32            // items per CTA iteration
#define WSTRIDE 132           // padded row stride (floats) -> bank-conflict-free
#define GEMM_GRID 148

__device__ __align__(16) float g_Wt[C_PAD * D_DIM];     // [c][d], tf32-rounded
__device__ __align__(16) float g_logits[(size_t)N_MAX * C_PAD];
__device__ float g_it2[N_MAX];
__device__ float g_UM[B_USERS * M_DIM];
__device__ float g_u2[B_USERS];
__device__ float g_G[M_DIM * M_DIM];

__device__ __forceinline__ unsigned f2tf32(float x) {
    unsigned r;
    asm("cvt.rna.tf32.f32 %0, %1;" : "=r"(r) : "f"(x));
    return r;
}

__device__ __forceinline__ void mma_tf32(float* c, const unsigned* a,
                                         unsigned b0, unsigned b1) {
    asm volatile(
        "mma.sync.aligned.m16n8k8.row.col.f32.tf32.tf32.f32 "
        "{%0,%1,%2,%3}, {%4,%5,%6,%7}, {%8,%9}, {%0,%1,%2,%3};"
        : "+f"(c[0]), "+f"(c[1]), "+f"(c[2]), "+f"(c[3])
        : "r"(a[0]), "r"(a[1]), "r"(a[2]), "r"(a[3]), "r"(b0), "r"(b1));
}

// ----------------------------------------------------------------------------
// Precompute (parallel): Wt (tf32-rounded), UM, u2, G.
// ----------------------------------------------------------------------------
__global__ void pre_kernel(const float* __restrict__ users,
                           const float* __restrict__ keyM,   // [D][M]
                           const float* __restrict__ mems,   // [M][D]
                           const void*  __restrict__ ids_raw)
{
    __shared__ int s_uid[B_USERS];
    const int tid = threadIdx.x;

    if (tid == 0) {
        // JAX without x64 silently downcasts int64 -> int32; sniff the layout.
        const long long* p64 = (const long long*)ids_raw;
        const int*       p32 = (const int*)ids_raw;
        bool is64 = true;
        for (int i = 0; i < 8; i++) {
            long long v = p64[i];
            if (v < 0 || v >= (1LL << 31)) is64 = false;
        }
        for (int i = 0; i < B_USERS; i++)
            s_uid[i] = is64 ? (int)p64[i] : p32[i];
    }
    __syncthreads();

    const int gtid  = blockIdx.x * blockDim.x + tid;
    const int gsize = gridDim.x * blockDim.x;

    // Wt[c][d]
    for (int idx = gtid; idx < C_PAD * D_DIM; idx += gsize) {
        int c = idx >> 7, d = idx & 127;
        float w = 0.f;
        if (c < B_USERS * 21) {
            int b = c / 21, j = c - b * 21;
            float u = users[(size_t)s_uid[b] * D_DIM + d];
            w = (j < M_DIM) ? u * keyM[d * M_DIM + j] : u;
        } else if (c < C_USE) {
            w = mems[(c - B_USERS * 21) * D_DIM + d];
        }
        g_Wt[idx] = __uint_as_float(f2tf32(w));
    }

    // UM[b][m]
    for (int t = gtid; t < B_USERS * M_DIM; t += gsize) {
        int b = t / M_DIM, m = t % M_DIM;
        const float* u = users + (size_t)s_uid[b] * D_DIM;
        const float* mv = mems + m * D_DIM;
        float s = 0.f;
        for (int d = 0; d < D_DIM; d++) s += u[d] * mv[d];
        g_UM[t] = s;
    }

    // |u_b|^2
    for (int t = gtid; t < B_USERS; t += gsize) {
        const float* u = users + (size_t)s_uid[t] * D_DIM;
        float s = 0.f;
        for (int d = 0; d < D_DIM; d++) s += u[d] * u[d];
        g_u2[t] = s;
    }

    // G[m][m']
    for (int t = gtid; t < M_DIM * M_DIM; t += gsize) {
        int m = t / M_DIM, mm = t % M_DIM;
        float s = 0.f;
        for (int d = 0; d < D_DIM; d++)
            s += mems[m * D_DIM + d] * mems[mm * D_DIM + d];
        g_G[t] = s;
    }
}

// ----------------------------------------------------------------------------
// Tensor-core GEMM: logits[n][c], 148 persistent CTAs, 8 warps each.
// W (tf32) resident in shared; warp w owns columns [48w, 48w+48).
// Per chunk: 32 items staged to shared, 2 row-subtiles x 6 col-frags of
// m16n8k8 tf32 mma. Also emits |item|^2.
// ----------------------------------------------------------------------------
__global__ void __launch_bounds__(256, 1)
gemm_kernel(const float* __restrict__ items, int N)
{
    extern __shared__ float smem[];
    float* Ws = smem;                         // [C_PAD][WSTRIDE]
    float* As = smem + C_PAD * WSTRIDE;       // [CHUNK][WSTRIDE]

    const int tid  = threadIdx.x;
    const int warp = tid >> 5;
    const int lane = tid & 31;
    const int g    = lane >> 2;     // groupID
    const int tig  = lane & 3;      // thread-in-group
    const int wcol = warp * 48;

    // Stage W (already tf32-rounded), float4 path
    {
        const float4* Wg = (const float4*)g_Wt;
        for (int i = tid; i < C_PAD * 32; i += 256) {
            int c = i >> 5, k4 = i & 31;
            *(float4*)&Ws[c * WSTRIDE + k4 * 4] = Wg[i];
        }
    }
    __syncthreads();

    const float4* itemsv = (const float4*)items;

    for (int base = blockIdx.x * CHUNK; base < N; base += gridDim.x * CHUNK) {
        // ---- stage A (tf32-rounded) ----
        for (int i = tid; i < CHUNK * 32; i += 256) {
            int r = i >> 5, k4 = i & 31;
            int n = base + r;
            float4 v = (n < N) ? itemsv[(size_t)n * 32 + k4]
                               : make_float4(0.f, 0.f, 0.f, 0.f);
            v.x = __uint_as_float(f2tf32(v.x));
            v.y = __uint_as_float(f2tf32(v.y));
            v.z = __uint_as_float(f2tf32(v.z));
            v.w = __uint_as_float(f2tf32(v.w));
            *(float4*)&As[r * WSTRIDE + k4 * 4] = v;
        }
        __syncthreads();

        // ---- |item|^2 (8 threads per row) ----
        {
            int r = tid >> 3, off = (tid & 7) * 16;
            const float4* p = (const float4*)&As[r * WSTRIDE + off];
            float s = 0.f;
#pragma unroll
            for (int j = 0; j < 4; j++) {
                float4 v = p[j];
                s += v.x * v.x + v.y * v.y + v.z * v.z + v.w * v.w;
            }
#pragma unroll
            for (int o = 4; o; o >>= 1)
                s += __shfl_down_sync(0xffffffffu, s, o, 8);
            if ((tid & 7) == 0 && base + r < N) g_it2[base + r] = s;
        }

        // ---- mma mainloop ----
        float acc[2][6][4];
#pragma unroll
        for (int s = 0; s < 2; s++)
#pragma unroll
            for (int j = 0; j < 6; j++)
#pragma unroll
                for (int q = 0; q < 4; q++) acc[s][j][q] = 0.f;

#pragma unroll
        for (int kk = 0; kk < 16; kk++) {
            const int k0 = kk * 8;
            unsigned a[2][4];
#pragma unroll
            for (int s = 0; s < 2; s++) {
                int rb = s * 16;
                a[s][0] = __float_as_uint(As[(rb + g)     * WSTRIDE + k0 + tig]);
                a[s][1] = __float_as_uint(As[(rb + g + 8) * WSTRIDE + k0 + tig]);
                a[s][2] = __float_as_uint(As[(rb + g)     * WSTRIDE + k0 + 4 + tig]);
                a[s][3] = __float_as_uint(As[(rb + g + 8) * WSTRIDE + k0 + 4 + tig]);
            }
#pragma unroll
            for (int j = 0; j < 6; j++) {
                int c = wcol + j * 8 + g;
                unsigned b0 = __float_as_uint(Ws[c * WSTRIDE + k0 + tig]);
                unsigned b1 = __float_as_uint(Ws[c * WSTRIDE + k0 + 4 + tig]);
                mma_tf32(acc[0][j], a[0], b0, b1);
                mma_tf32(acc[1][j], a[1], b0, b1);
            }
        }

        // ---- store logits ----
#pragma unroll
        for (int s = 0; s < 2; s++) {
#pragma unroll
            for (int j = 0; j < 6; j++) {
                int col = wcol + j * 8 + 2 * tig;
                int r0 = base + s * 16 + g;
                int r1 = r0 + 8;
                if (r0 < N) {
                    float2 v = make_float2(acc[s][j][0], acc[s][j][1]);
                    *(float2*)&g_logits[(size_t)r0 * C_PAD + col] = v;
                }
                if (r1 < N) {
                    float2 v = make_float2(acc[s][j][2], acc[s][j][3]);
                    *(float2*)&g_logits[(size_t)r1 * C_PAD + col] = v;
                }
            }
        }
        __syncthreads();   // As fully consumed before restaging
    }
}

// ----------------------------------------------------------------------------
// Epilogue: per (b,n): softmax over M, Gram quadratic form, distance.
// ----------------------------------------------------------------------------
__global__ void epi_kernel(float* __restrict__ out, int N)
{
    __shared__ float Gs[M_DIM * M_DIM];
    __shared__ float UMs[B_USERS * M_DIM];
    __shared__ float u2s[B_USERS];

    const int tid = threadIdx.x;
    for (int i = tid; i < M_DIM * M_DIM; i += blockDim.x) Gs[i] = g_G[i];
    for (int i = tid; i < B_USERS * M_DIM; i += blockDim.x) UMs[i] = g_UM[i];
    if (tid < B_USERS) u2s[tid] = g_u2[tid];
    __syncthreads();

    long long idx = (long long)blockIdx.x * blockDim.x + tid;
    if (idx >= (long long)B_USERS * N) return;
    int b = (int)(idx & (B_USERS - 1));
    int n = (int)(idx >> 4);

    const float* row = g_logits + (size_t)n * C_PAD;
    const float* lb = row + b * 21;

    float l[M_DIM];
#pragma unroll
    for (int j = 0; j < M_DIM; j++) l[j] = lb[j];
    float uit = lb[M_DIM];

    float mx = l[0];
#pragma unroll
    for (int j = 1; j < M_DIM; j++) mx = fmaxf(mx, l[j]);

    float e[M_DIM];
    float S = 0.f;
#pragma unroll
    for (int j = 0; j < M_DIM; j++) { e[j] = __expf(l[j] - mx); S += e[j]; }

    float num1 = 0.f;
#pragma unroll
    for (int j = 0; j < M_DIM; j++)
        num1 += e[j] * (UMs[b * M_DIM + j] - row[B_USERS * 21 + j]);

    float Q = 0.f;
#pragma unroll 4
    for (int m = 0; m < M_DIM; m++) {
        float gv = 0.f;
#pragma unroll
        for (int j = 0; j < M_DIM; j++)
            gv += Gs[m * M_DIM + j] * e[j];
        Q += e[m] * gv;
    }

    float invS = 1.f / S;
    float s2 = u2s[b] + g_it2[n] - 2.f * uit + 2.f * num1 * invS + Q * invS * invS;
    out[(size_t)b * N + n] = -sqrtf(fmaxf(s2, 0.f));
}

// ----------------------------------------------------------------------------
extern "C" void kernel_launch(void* const* d_in, const int* in_sizes, int n_in,
                              void* d_out, int out_size)
{
    const float* users = (const float*)d_in[0];
    const float* items = (const float*)d_in[1];
    const float* keyM  = (const float*)d_in[2];
    const float* mems  = (const float*)d_in[3];
    const void*  ids   = d_in[4];
    float* out = (float*)d_out;

    const int N = in_sizes[1] / D_DIM;

    const int smem_bytes = (C_PAD + CHUNK) * WSTRIDE * 4;   // 219,648 B
    cudaFuncSetAttribute(gemm_kernel,
                         cudaFuncAttributeMaxDynamicSharedMemorySize, smem_bytes);

    pre_kernel<<<64, 256>>>(users, keyM, mems, ids);
    gemm_kernel<<<GEMM_GRID, 256, smem_bytes>>>(items, N);

    long long total = (long long)B_USERS * N;
    int blocks = (int)((total + 255) / 256);
    epi_kernel<<<blocks, 256>>>(out, N);
}

// round 3
// speedup vs baseline: 2.5635x; 1.0611x over previous
#include <cuda_runtime.h>
#include <cuda_bf16.h>

// ============================================================================
// LRML scoring, restructured + tensor-core GEMM (tf32 mma.sync):
//   logits[n,c] = item[n,:] @ Wt[c,:]   for columns:
//     c in [0,336): b*21+m -> u_b[d]*K[d,m];  b*21+20 -> u_b[d] (u.item)
//     c in [336,356): mem_m[d]                (IM columns)
//   score^2 = |u|^2 + |item|^2 - 2 u.item + 2 att.(UM - IM) + att^T G att
// R3: W built in-GEMM (no pre W pass); epi reads logits via coalesced
//     shared staging (fixes L1tex wavefront blowup); f32x2 epi math.
// ============================================================================

#define D_DIM   128
#define M_DIM   20
#define B_USERS 16
#define N_MAX   50000
#define C_USE   356
#define C_PAD   384
#define CHUNK   32
#define WSTRIDE 132
#define GEMM_GRID 148
#define EPI_ROWS 16
#define EPI_STRIDE 388

__device__ __align__(16) float g_logits[(size_t)N_MAX * C_PAD];
__device__ float g_it2[N_MAX];
__device__ float g_UM[B_USERS * M_DIM];
__device__ float g_u2[B_USERS];
__device__ float g_G[M_DIM * M_DIM];

__device__ __forceinline__ unsigned f2tf32(float x) {
    unsigned r;
    asm("cvt.rna.tf32.f32 %0, %1;" : "=r"(r) : "f"(x));
    return r;
}

__device__ __forceinline__ void mma_tf32(float* c, const unsigned* a,
                                         unsigned b0, unsigned b1) {
    asm volatile(
        "mma.sync.aligned.m16n8k8.row.col.f32.tf32.tf32.f32 "
        "{%0,%1,%2,%3}, {%4,%5,%6,%7}, {%8,%9}, {%0,%1,%2,%3};"
        : "+f"(c[0]), "+f"(c[1]), "+f"(c[2]), "+f"(c[3])
        : "r"(a[0]), "r"(a[1]), "r"(a[2]), "r"(a[3]), "r"(b0), "r"(b1));
}

__device__ __forceinline__ float2 ffma2(float2 a, float2 b, float2 c) {
    unsigned long long ra = *reinterpret_cast<unsigned long long*>(&a);
    unsigned long long rb = *reinterpret_cast<unsigned long long*>(&b);
    unsigned long long rc = *reinterpret_cast<unsigned long long*>(&c);
    unsigned long long rd;
    asm("fma.rn.f32x2 %0, %1, %2, %3;" : "=l"(rd) : "l"(ra), "l"(rb), "l"(rc));
    return *reinterpret_cast<float2*>(&rd);
}

// ids may be int64 or (silently downcast) int32 — sniff layout.
__device__ __forceinline__ void sniff_uids(const void* ids_raw, int* s_uid) {
    const long long* p64 = (const long long*)ids_raw;
    const int*       p32 = (const int*)ids_raw;
    bool is64 = true;
    for (int i = 0; i < 8; i++) {
        long long v = p64[i];
        if (v < 0 || v >= (1LL << 31)) is64 = false;
    }
    for (int i = 0; i < B_USERS; i++)
        s_uid[i] = is64 ? (int)p64[i] : p32[i];
}

// ----------------------------------------------------------------------------
// pre2: UM, u2, G via one warp per 128-d dot product (736 dots).
// ----------------------------------------------------------------------------
__global__ void pre2_kernel(const float* __restrict__ users,
                            const float* __restrict__ mems,
                            const void*  __restrict__ ids_raw)
{
    __shared__ int s_uid[B_USERS];
    if (threadIdx.x == 0) sniff_uids(ids_raw, s_uid);
    __syncthreads();

    const int w = blockIdx.x * (blockDim.x >> 5) + (threadIdx.x >> 5);
    const int lane = threadIdx.x & 31;
    const int TOTAL = B_USERS * M_DIM + B_USERS + M_DIM * M_DIM;  // 736
    if (w >= TOTAL) return;

    const float4* pa;
    const float4* pb;
    float* dst;
    if (w < B_USERS * M_DIM) {
        int b = w / M_DIM, m = w % M_DIM;
        pa = (const float4*)(users + (size_t)s_uid[b] * D_DIM);
        pb = (const float4*)(mems + m * D_DIM);
        dst = &g_UM[w];
    } else if (w < B_USERS * M_DIM + B_USERS) {
        int b = w - B_USERS * M_DIM;
        pa = (const float4*)(users + (size_t)s_uid[b] * D_DIM);
        pb = pa;
        dst = &g_u2[b];
    } else {
        int t = w - B_USERS * M_DIM - B_USERS;
        pa = (const float4*)(mems + (t / M_DIM) * D_DIM);
        pb = (const float4*)(mems + (t % M_DIM) * D_DIM);
        dst = &g_G[t];
    }
    float4 a = pa[lane], b = pb[lane];
    float s = a.x * b.x + a.y * b.y + a.z * b.z + a.w * b.w;
#pragma unroll
    for (int o = 16; o; o >>= 1) s += __shfl_xor_sync(0xffffffffu, s, o);
    if (lane == 0) *dst = s;
}

// ----------------------------------------------------------------------------
// Tensor-core GEMM: 148 persistent CTAs, 8 warps. W built in shared per-CTA.
// ----------------------------------------------------------------------------
__global__ void __launch_bounds__(256, 1)
gemm_kernel(const float* __restrict__ items,
            const float* __restrict__ users,
            const float* __restrict__ keyM,
            const float* __restrict__ mems,
            const void*  __restrict__ ids_raw, int N)
{
    extern __shared__ float smem[];
    float* Ws = smem;                         // [C_PAD][WSTRIDE]
    float* As = smem + C_PAD * WSTRIDE;       // [CHUNK][WSTRIDE]

    __shared__ int s_uid[B_USERS];

    const int tid  = threadIdx.x;
    const int warp = tid >> 5;
    const int lane = tid & 31;
    const int g    = lane >> 2;
    const int tig  = lane & 3;
    const int wcol = warp * 48;

    if (tid == 0) sniff_uids(ids_raw, s_uid);
    __syncthreads();

    // Build W (tf32-rounded) directly into shared
    for (int idx = tid; idx < C_PAD * D_DIM; idx += 256) {
        int c = idx >> 7, d = idx & 127;
        float w = 0.f;
        if (c < B_USERS * 21) {
            int b = c / 21, j = c - b * 21;
            float u = users[(size_t)s_uid[b] * D_DIM + d];
            w = (j < M_DIM) ? u * keyM[d * M_DIM + j] : u;
        } else if (c < C_USE) {
            w = mems[(c - B_USERS * 21) * D_DIM + d];
        }
        Ws[c * WSTRIDE + d] = __uint_as_float(f2tf32(w));
    }
    __syncthreads();

    const float4* itemsv = (const float4*)items;

    for (int base = blockIdx.x * CHUNK; base < N; base += gridDim.x * CHUNK) {
        // ---- stage A (tf32-rounded) ----
        for (int i = tid; i < CHUNK * 32; i += 256) {
            int r = i >> 5, k4 = i & 31;
            int n = base + r;
            float4 v = (n < N) ? itemsv[(size_t)n * 32 + k4]
                               : make_float4(0.f, 0.f, 0.f, 0.f);
            v.x = __uint_as_float(f2tf32(v.x));
            v.y = __uint_as_float(f2tf32(v.y));
            v.z = __uint_as_float(f2tf32(v.z));
            v.w = __uint_as_float(f2tf32(v.w));
            *(float4*)&As[r * WSTRIDE + k4 * 4] = v;
        }
        __syncthreads();

        // ---- |item|^2 (8 threads per row) ----
        {
            int r = tid >> 3, off = (tid & 7) * 16;
            const float4* p = (const float4*)&As[r * WSTRIDE + off];
            float s = 0.f;
#pragma unroll
            for (int j = 0; j < 4; j++) {
                float4 v = p[j];
                s += v.x * v.x + v.y * v.y + v.z * v.z + v.w * v.w;
            }
#pragma unroll
            for (int o = 4; o; o >>= 1)
                s += __shfl_down_sync(0xffffffffu, s, o, 8);
            if ((tid & 7) == 0 && base + r < N) g_it2[base + r] = s;
        }

        // ---- mma mainloop ----
        float acc[2][6][4];
#pragma unroll
        for (int s = 0; s < 2; s++)
#pragma unroll
            for (int j = 0; j < 6; j++)
#pragma unroll
                for (int q = 0; q < 4; q++) acc[s][j][q] = 0.f;

#pragma unroll
        for (int kk = 0; kk < 16; kk++) {
            const int k0 = kk * 8;
            unsigned a[2][4];
#pragma unroll
            for (int s = 0; s < 2; s++) {
                int rb = s * 16;
                a[s][0] = __float_as_uint(As[(rb + g)     * WSTRIDE + k0 + tig]);
                a[s][1] = __float_as_uint(As[(rb + g + 8) * WSTRIDE + k0 + tig]);
                a[s][2] = __float_as_uint(As[(rb + g)     * WSTRIDE + k0 + 4 + tig]);
                a[s][3] = __float_as_uint(As[(rb + g + 8) * WSTRIDE + k0 + 4 + tig]);
            }
#pragma unroll
            for (int j = 0; j < 6; j++) {
                int c = wcol + j * 8 + g;
                unsigned b0 = __float_as_uint(Ws[c * WSTRIDE + k0 + tig]);
                unsigned b1 = __float_as_uint(Ws[c * WSTRIDE + k0 + 4 + tig]);
                mma_tf32(acc[0][j], a[0], b0, b1);
                mma_tf32(acc[1][j], a[1], b0, b1);
            }
        }

        // ---- store logits (skip dead pad columns >= C_USE) ----
#pragma unroll
        for (int s = 0; s < 2; s++) {
#pragma unroll
            for (int j = 0; j < 6; j++) {
                int col = wcol + j * 8 + 2 * tig;
                if (col >= C_USE) continue;
                int r0 = base + s * 16 + g;
                int r1 = r0 + 8;
                if (r0 < N) {
                    float2 v = make_float2(acc[s][j][0], acc[s][j][1]);
                    *(float2*)&g_logits[(size_t)r0 * C_PAD + col] = v;
                }
                if (r1 < N) {
                    float2 v = make_float2(acc[s][j][2], acc[s][j][3]);
                    *(float2*)&g_logits[(size_t)r1 * C_PAD + col] = v;
                }
            }
        }
        __syncthreads();
    }
}

// ----------------------------------------------------------------------------
// Epilogue: block stages EPI_ROWS logits rows coalesced into shared, then
// per-(b,n) softmax + Gram quadratic form with f32x2 math.
// ----------------------------------------------------------------------------
__global__ void __launch_bounds__(256)
epi_kernel(float* __restrict__ out, int N)
{
    __shared__ float rows[EPI_ROWS * EPI_STRIDE];
    __shared__ float Gs[M_DIM * M_DIM];
    __shared__ float UMs[B_USERS * M_DIM];
    __shared__ float u2s[B_USERS];
    __shared__ float it2s[EPI_ROWS];

    const int tid = threadIdx.x;
    const int base = blockIdx.x * EPI_ROWS;

    for (int i = tid; i < M_DIM * M_DIM; i += 256) Gs[i] = g_G[i];
    for (int i = tid; i < B_USERS * M_DIM; i += 256) UMs[i] = g_UM[i];
    if (tid < B_USERS) u2s[tid] = g_u2[tid];
    if (tid < EPI_ROWS && base + tid < N) it2s[tid] = g_it2[base + tid];

    // Coalesced staging: 16 rows x 90 float4 (360 floats covers C_USE=356)
    for (int i = tid; i < EPI_ROWS * 90; i += 256) {
        int r = i / 90, c4 = i - r * 90;
        if (base + r < N) {
            float4 v = *(const float4*)&g_logits[(size_t)(base + r) * C_PAD + c4 * 4];
            *(float4*)&rows[r * EPI_STRIDE + c4 * 4] = v;
        }
    }
    __syncthreads();

    const int b  = tid & (B_USERS - 1);
    const int nl = tid >> 4;
    const int n  = base + nl;
    if (n >= N) return;

    const float* srow = &rows[nl * EPI_STRIDE];
    const float* lb = srow + b * 21;

    float l[M_DIM];
#pragma unroll
    for (int j = 0; j < M_DIM; j++) l[j] = lb[j];
    float uit = lb[M_DIM];

    float mx = l[0];
#pragma unroll
    for (int j = 1; j < M_DIM; j++) mx = fmaxf(mx, l[j]);

    float2 e2[M_DIM / 2];
    float S = 0.f;
#pragma unroll
    for (int j = 0; j < M_DIM / 2; j++) {
        float ea = __expf(l[2 * j] - mx);
        float eb = __expf(l[2 * j + 1] - mx);
        e2[j] = make_float2(ea, eb);
        S += ea + eb;
    }

    // num1 = e . (UM - IM)
    float2 acc1 = make_float2(0.f, 0.f);
#pragma unroll
    for (int j = 0; j < M_DIM / 2; j++) {
        float2 um = *(const float2*)&UMs[b * M_DIM + 2 * j];
        float2 im = *(const float2*)&srow[B_USERS * 21 + 2 * j];
        acc1 = ffma2(e2[j], make_float2(um.x - im.x, um.y - im.y), acc1);
    }
    float num1 = acc1.x + acc1.y;

    // Q = e^T G e
    float Q = 0.f;
#pragma unroll
    for (int m2 = 0; m2 < M_DIM / 2; m2++) {
        float2 qa = make_float2(0.f, 0.f);
        float2 qb = make_float2(0.f, 0.f);
        const float2* Gr0 = (const float2*)&Gs[(2 * m2) * M_DIM];
        const float2* Gr1 = (const float2*)&Gs[(2 * m2 + 1) * M_DIM];
#pragma unroll
        for (int j = 0; j < M_DIM / 2; j++) {
            qa = ffma2(Gr0[j], e2[j], qa);
            qb = ffma2(Gr1[j], e2[j], qb);
        }
        Q += e2[m2].x * (qa.x + qa.y) + e2[m2].y * (qb.x + qb.y);
    }

    float invS = 1.f / S;
    float s2 = u2s[b] + it2s[nl] - 2.f * uit + 2.f * num1 * invS + Q * invS * invS;
    out[(size_t)b * N + n] = -sqrtf(fmaxf(s2, 0.f));
}

// ----------------------------------------------------------------------------
extern "C" void kernel_launch(void* const* d_in, const int* in_sizes, int n_in,
                              void* d_out, int out_size)
{
    const float* users = (const float*)d_in[0];
    const float* items = (const float*)d_in[1];
    const float* keyM  = (const float*)d_in[2];
    const float* mems  = (const float*)d_in[3];
    const void*  ids   = d_in[4];
    float* out = (float*)d_out;

    const int N = in_sizes[1] / D_DIM;

    const int smem_bytes = (C_PAD + CHUNK) * WSTRIDE * 4;   // 219,648 B
    cudaFuncSetAttribute(gemm_kernel,
                         cudaFuncAttributeMaxDynamicSharedMemorySize, smem_bytes);

    pre2_kernel<<<92, 256>>>(users, mems, ids);
    gemm_kernel<<<GEMM_GRID, 256, smem_bytes>>>(items, users, keyM, mems, ids, N);
    epi_kernel<<<(N + EPI_ROWS - 1) / EPI_ROWS, 256>>>(out, N);
}

// round 4
// speedup vs baseline: 3.2883x; 1.2827x over previous
#include <cuda_runtime.h>
#include <cuda_bf16.h>

// ============================================================================
// LRML scoring, fully fused:
//   Per CTA chunk of 16 items: logits[16,360] = items @ W  (tf32 mma.sync),
//   then softmax/Gram epilogue in-CTA, writing only out[b,n].
//   Columns: c in [0,336): b*21+m -> u_b[d]*K[d,m]; b*21+20 -> u_b[d]
//            c in [336,356): mem_m[d]    (IM);  [356,360) zero pad
//   score^2 = |u|^2 + |item|^2 - 2 u.item + 2 att.(UM - IM) + att^T G att
// ============================================================================

#define D_DIM   128
#define M_DIM   20
#define B_USERS 16
#define C_USE   356
#define C_W     360            // 45 n-frags of 8
#define NFRAGS  45
#define CHUNK   16
#define WSTRIDE 132
#define LSTRIDE 362
#define GEMM_GRID 148

__device__ float g_UM[B_USERS * M_DIM];
__device__ float g_u2[B_USERS];
__device__ float g_G[M_DIM * M_DIM];

__device__ __forceinline__ unsigned f2tf32(float x) {
    unsigned r;
    asm("cvt.rna.tf32.f32 %0, %1;" : "=r"(r) : "f"(x));
    return r;
}

__device__ __forceinline__ void mma_tf32(float* c, const unsigned* a,
                                         unsigned b0, unsigned b1) {
    asm volatile(
        "mma.sync.aligned.m16n8k8.row.col.f32.tf32.tf32.f32 "
        "{%0,%1,%2,%3}, {%4,%5,%6,%7}, {%8,%9}, {%0,%1,%2,%3};"
        : "+f"(c[0]), "+f"(c[1]), "+f"(c[2]), "+f"(c[3])
        : "r"(a[0]), "r"(a[1]), "r"(a[2]), "r"(a[3]), "r"(b0), "r"(b1));
}

__device__ __forceinline__ float2 ffma2(float2 a, float2 b, float2 c) {
    unsigned long long ra = *reinterpret_cast<unsigned long long*>(&a);
    unsigned long long rb = *reinterpret_cast<unsigned long long*>(&b);
    unsigned long long rc = *reinterpret_cast<unsigned long long*>(&c);
    unsigned long long rd;
    asm("fma.rn.f32x2 %0, %1, %2, %3;" : "=l"(rd) : "l"(ra), "l"(rb), "l"(rc));
    return *reinterpret_cast<float2*>(&rd);
}

// ids may be int64 or (silently downcast) int32 — sniff layout.
__device__ __forceinline__ void sniff_uids(const void* ids_raw, int* s_uid) {
    const long long* p64 = (const long long*)ids_raw;
    const int*       p32 = (const int*)ids_raw;
    bool is64 = true;
    for (int i = 0; i < 8; i++) {
        long long v = p64[i];
        if (v < 0 || v >= (1LL << 31)) is64 = false;
    }
    for (int i = 0; i < B_USERS; i++)
        s_uid[i] = is64 ? (int)p64[i] : p32[i];
}

// ----------------------------------------------------------------------------
// pre2: UM, u2, G via one warp per 128-d dot product (736 dots).
// ----------------------------------------------------------------------------
__global__ void pre2_kernel(const float* __restrict__ users,
                            const float* __restrict__ mems,
                            const void*  __restrict__ ids_raw)
{
    __shared__ int s_uid[B_USERS];
    if (threadIdx.x == 0) sniff_uids(ids_raw, s_uid);
    __syncthreads();

    const int w = blockIdx.x * (blockDim.x >> 5) + (threadIdx.x >> 5);
    const int lane = threadIdx.x & 31;
    const int TOTAL = B_USERS * M_DIM + B_USERS + M_DIM * M_DIM;  // 736
    if (w >= TOTAL) return;

    const float4* pa;
    const float4* pb;
    float* dst;
    if (w < B_USERS * M_DIM) {
        int b = w / M_DIM, m = w % M_DIM;
        pa = (const float4*)(users + (size_t)s_uid[b] * D_DIM);
        pb = (const float4*)(mems + m * D_DIM);
        dst = &g_UM[w];
    } else if (w < B_USERS * M_DIM + B_USERS) {
        int b = w - B_USERS * M_DIM;
        pa = (const float4*)(users + (size_t)s_uid[b] * D_DIM);
        pb = pa;
        dst = &g_u2[b];
    } else {
        int t = w - B_USERS * M_DIM - B_USERS;
        pa = (const float4*)(mems + (t / M_DIM) * D_DIM);
        pb = (const float4*)(mems + (t % M_DIM) * D_DIM);
        dst = &g_G[t];
    }
    float4 a = pa[lane], b = pb[lane];
    float s = a.x * b.x + a.y * b.y + a.z * b.z + a.w * b.w;
#pragma unroll
    for (int o = 16; o; o >>= 1) s += __shfl_xor_sync(0xffffffffu, s, o);
    if (lane == 0) *dst = s;
}

// ----------------------------------------------------------------------------
// Fused GEMM + epilogue: 148 persistent CTAs, 8 warps.
// ----------------------------------------------------------------------------
__global__ void __launch_bounds__(256, 1)
fused_kernel(const float* __restrict__ items,
             const float* __restrict__ users,
             const float* __restrict__ keyM,
             const float* __restrict__ mems,
             const void*  __restrict__ ids_raw,
             float* __restrict__ out, int N)
{
    extern __shared__ float smem[];
    float* Ws = smem;                                  // [C_W][WSTRIDE]
    float* As = smem + C_W * WSTRIDE;                  // [CHUNK][WSTRIDE]
    float* Ls = As + CHUNK * WSTRIDE;                  // [CHUNK][LSTRIDE]

    __shared__ int s_uid[B_USERS];
    __shared__ float Gs[M_DIM * M_DIM];
    __shared__ float UMs[B_USERS * M_DIM];
    __shared__ float u2s[B_USERS];
    __shared__ float it2s[CHUNK];

    const int tid  = threadIdx.x;
    const int warp = tid >> 5;
    const int lane = tid & 31;
    const int g    = lane >> 2;
    const int tig  = lane & 3;

    if (tid == 0) sniff_uids(ids_raw, s_uid);
    for (int i = tid; i < M_DIM * M_DIM; i += 256) Gs[i] = g_G[i];
    for (int i = tid; i < B_USERS * M_DIM; i += 256) UMs[i] = g_UM[i];
    if (tid < B_USERS) u2s[tid] = g_u2[tid];
    __syncthreads();

    // Build W (tf32-rounded) directly into shared
    for (int idx = tid; idx < C_W * D_DIM; idx += 256) {
        int c = idx >> 7, d = idx & 127;
        float w = 0.f;
        if (c < B_USERS * 21) {
            int b = c / 21, j = c - b * 21;
            float u = users[(size_t)s_uid[b] * D_DIM + d];
            w = (j < M_DIM) ? u * keyM[d * M_DIM + j] : u;
        } else if (c < C_USE) {
            w = mems[(c - B_USERS * 21) * D_DIM + d];
        }
        Ws[c * WSTRIDE + d] = __uint_as_float(f2tf32(w));
    }
    __syncthreads();

    const float4* itemsv = (const float4*)items;

    for (int base = blockIdx.x * CHUNK; base < N; base += gridDim.x * CHUNK) {
        // ---- stage A (tf32-rounded), 16 rows x 32 float4 ----
        for (int i = tid; i < CHUNK * 32; i += 256) {
            int r = i >> 5, k4 = i & 31;
            int n = base + r;
            float4 v = (n < N) ? itemsv[(size_t)n * 32 + k4]
                               : make_float4(0.f, 0.f, 0.f, 0.f);
            v.x = __uint_as_float(f2tf32(v.x));
            v.y = __uint_as_float(f2tf32(v.y));
            v.z = __uint_as_float(f2tf32(v.z));
            v.w = __uint_as_float(f2tf32(v.w));
            *(float4*)&As[r * WSTRIDE + k4 * 4] = v;
        }
        __syncthreads();

        // ---- |item|^2 (16 threads per row) ----
        if (tid < 256) {
            int r = tid >> 4, off = (tid & 15) * 8;
            const float4* p = (const float4*)&As[r * WSTRIDE + off];
            float4 v0 = p[0], v1 = p[1];
            float s = v0.x * v0.x + v0.y * v0.y + v0.z * v0.z + v0.w * v0.w
                    + v1.x * v1.x + v1.y * v1.y + v1.z * v1.z + v1.w * v1.w;
#pragma unroll
            for (int o = 8; o; o >>= 1)
                s += __shfl_down_sync(0xffffffffu, s, o, 16);
            if ((tid & 15) == 0) it2s[r] = s;
        }

        // ---- mma mainloop: warp handles frags f = warp + 8j (f < 45) ----
        float acc[6][4];
#pragma unroll
        for (int j = 0; j < 6; j++)
#pragma unroll
            for (int q = 0; q < 4; q++) acc[j][q] = 0.f;

#pragma unroll
        for (int kk = 0; kk < 16; kk++) {
            const int k0 = kk * 8;
            unsigned a[4];
            a[0] = __float_as_uint(As[g        * WSTRIDE + k0 + tig]);
            a[1] = __float_as_uint(As[(g + 8)  * WSTRIDE + k0 + tig]);
            a[2] = __float_as_uint(As[g        * WSTRIDE + k0 + 4 + tig]);
            a[3] = __float_as_uint(As[(g + 8)  * WSTRIDE + k0 + 4 + tig]);
#pragma unroll
            for (int j = 0; j < 6; j++) {
                int f = warp + 8 * j;
                if (f < NFRAGS) {
                    int c = f * 8 + g;
                    unsigned b0 = __float_as_uint(Ws[c * WSTRIDE + k0 + tig]);
                    unsigned b1 = __float_as_uint(Ws[c * WSTRIDE + k0 + 4 + tig]);
                    mma_tf32(acc[j], a, b0, b1);
                }
            }
        }

        // ---- dump acc to Ls ----
#pragma unroll
        for (int j = 0; j < 6; j++) {
            int f = warp + 8 * j;
            if (f < NFRAGS) {
                int col = f * 8 + 2 * tig;
                *(float2*)&Ls[g * LSTRIDE + col] =
                    make_float2(acc[j][0], acc[j][1]);
                *(float2*)&Ls[(g + 8) * LSTRIDE + col] =
                    make_float2(acc[j][2], acc[j][3]);
            }
        }
        __syncthreads();

        // ---- epilogue: thread (b = tid>>4, nl = tid&15) ----
        {
            const int b  = tid >> 4;
            const int nl = tid & 15;
            const int n  = base + nl;
            if (n < N) {
                const float* srow = &Ls[nl * LSTRIDE];
                const float* lb = srow + b * 21;

                float l[M_DIM];
#pragma unroll
                for (int j = 0; j < M_DIM; j++) l[j] = lb[j];
                float uit = lb[M_DIM];

                float mx = l[0];
#pragma unroll
                for (int j = 1; j < M_DIM; j++) mx = fmaxf(mx, l[j]);

                float2 e2[M_DIM / 2];
                float S = 0.f;
#pragma unroll
                for (int j = 0; j < M_DIM / 2; j++) {
                    float ea = __expf(l[2 * j] - mx);
                    float eb = __expf(l[2 * j + 1] - mx);
                    e2[j] = make_float2(ea, eb);
                    S += ea + eb;
                }

                // num1 = e . (UM - IM)
                float2 acc1 = make_float2(0.f, 0.f);
#pragma unroll
                for (int j = 0; j < M_DIM / 2; j++) {
                    float2 um = *(const float2*)&UMs[b * M_DIM + 2 * j];
                    float2 im = *(const float2*)&srow[B_USERS * 21 + 2 * j];
                    acc1 = ffma2(e2[j], make_float2(um.x - im.x, um.y - im.y), acc1);
                }
                float num1 = acc1.x + acc1.y;

                // Q = e^T G e
                float Q = 0.f;
#pragma unroll
                for (int m2 = 0; m2 < M_DIM / 2; m2++) {
                    float2 qa = make_float2(0.f, 0.f);
                    float2 qb = make_float2(0.f, 0.f);
                    const float2* Gr0 = (const float2*)&Gs[(2 * m2) * M_DIM];
                    const float2* Gr1 = (const float2*)&Gs[(2 * m2 + 1) * M_DIM];
#pragma unroll
                    for (int j = 0; j < M_DIM / 2; j++) {
                        qa = ffma2(Gr0[j], e2[j], qa);
                        qb = ffma2(Gr1[j], e2[j], qb);
                    }
                    Q += e2[m2].x * (qa.x + qa.y) + e2[m2].y * (qb.x + qb.y);
                }

                float invS = 1.f / S;
                float s2 = u2s[b] + it2s[nl] - 2.f * uit
                         + 2.f * num1 * invS + Q * invS * invS;
                out[(size_t)b * N + n] = -sqrtf(fmaxf(s2, 0.f));
            }
        }
        __syncthreads();   // Ls/As/it2s fully consumed before next chunk
    }
}

// ----------------------------------------------------------------------------
extern "C" void kernel_launch(void* const* d_in, const int* in_sizes, int n_in,
                              void* d_out, int out_size)
{
    const float* users = (const float*)d_in[0];
    const float* items = (const float*)d_in[1];
    const float* keyM  = (const float*)d_in[2];
    const float* mems  = (const float*)d_in[3];
    const void*  ids   = d_in[4];
    float* out = (float*)d_out;

    const int N = in_sizes[1] / D_DIM;

    const int smem_bytes = (C_W * WSTRIDE + CHUNK * WSTRIDE + CHUNK * LSTRIDE) * 4;
    cudaFuncSetAttribute(fused_kernel,
                         cudaFuncAttributeMaxDynamicSharedMemorySize, smem_bytes);

    pre2_kernel<<<92, 256>>>(users, mems, ids);
    fused_kernel<<<GEMM_GRID, 256, smem_bytes>>>(items, users, keyM, mems, ids, out, N);
}

// round 5
// speedup vs baseline: 3.4162x; 1.0389x over previous
#include <cuda_runtime.h>
#include <cuda_bf16.h>

// ============================================================================
// LRML scoring, fully fused, k-permuted swizzled smem + LDS.128 operands:
//   Per CTA chunk of 16 items: logits[16,360] = items @ W  (tf32 mma.sync),
//   softmax/Gram epilogue in-CTA, writes only out[b,n].
//   Columns: c in [0,336): b*21+m -> u_b[d]*K[d,m]; b*21+20 -> u_b[d]
//            c in [336,356): mem_m[d] (IM);  [356,360) zero pad
//   score^2 = |u|^2 + |item|^2 - 2 u.item + 2 att.(UM - IM) + att^T G att
//
// Smem row = 128 floats (512B). k-permutation: logical float4-chunk q=4p+tig
// holds k = 16p + tig + {0,4,8,12}  (p = k-pair index, 2 MMA k-steps).
// Physical chunk = 4*(p ^ (row&1)) + (tig ^ ((p>>1)&3))  -> conflict-free
// LDS.128 loads and conflict-free staging STS.128.
// ============================================================================

#define D_DIM   128
#define M_DIM   20
#define B_USERS 16
#define C_USE   356
#define C_W     360
#define NFRAGS  45
#define CHUNK   16
#define LSTRIDE 374
#define GRID    148

__device__ float g_UM[B_USERS * M_DIM];
__device__ float g_u2[B_USERS];
__device__ float g_G[M_DIM * M_DIM];

__device__ __forceinline__ unsigned f2tf32(float x) {
    unsigned r;
    asm("cvt.rna.tf32.f32 %0, %1;" : "=r"(r) : "f"(x));
    return r;
}
__device__ __forceinline__ float f2tf32f(float x) {
    return __uint_as_float(f2tf32(x));
}

__device__ __forceinline__ void mma_tf32(float* c, unsigned a0, unsigned a1,
                                         unsigned a2, unsigned a3,
                                         unsigned b0, unsigned b1) {
    asm volatile(
        "mma.sync.aligned.m16n8k8.row.col.f32.tf32.tf32.f32 "
        "{%0,%1,%2,%3}, {%4,%5,%6,%7}, {%8,%9}, {%0,%1,%2,%3};"
        : "+f"(c[0]), "+f"(c[1]), "+f"(c[2]), "+f"(c[3])
        : "r"(a0), "r"(a1), "r"(a2), "r"(a3), "r"(b0), "r"(b1));
}

__device__ __forceinline__ float2 ffma2(float2 a, float2 b, float2 c) {
    unsigned long long ra = *reinterpret_cast<unsigned long long*>(&a);
    unsigned long long rb = *reinterpret_cast<unsigned long long*>(&b);
    unsigned long long rc = *reinterpret_cast<unsigned long long*>(&c);
    unsigned long long rd;
    asm("fma.rn.f32x2 %0, %1, %2, %3;" : "=l"(rd) : "l"(ra), "l"(rb), "l"(rc));
    return *reinterpret_cast<float2*>(&rd);
}

// ids may be int64 or (silently downcast) int32 — sniff layout.
__device__ __forceinline__ void sniff_uids(const void* ids_raw, int* s_uid) {
    const long long* p64 = (const long long*)ids_raw;
    const int*       p32 = (const int*)ids_raw;
    bool is64 = true;
    for (int i = 0; i < 8; i++) {
        long long v = p64[i];
        if (v < 0 || v >= (1LL << 31)) is64 = false;
    }
    for (int i = 0; i < B_USERS; i++)
        s_uid[i] = is64 ? (int)p64[i] : p32[i];
}

// physical float index within a 128-float row for logical element d, row parity xb
__device__ __forceinline__ int swz_pos(int d, int xb) {
    int p = d >> 4, r16 = d & 15;
    int tig0 = r16 & 3, slot = r16 >> 2;
    int chunk = 4 * (p ^ xb) + (tig0 ^ ((p >> 1) & 3));
    return chunk * 4 + slot;
}

// ----------------------------------------------------------------------------
// pre2: UM, u2, G via one warp per 128-d dot product (736 dots).
// ----------------------------------------------------------------------------
__global__ void pre2_kernel(const float* __restrict__ users,
                            const float* __restrict__ mems,
                            const void*  __restrict__ ids_raw)
{
    __shared__ int s_uid[B_USERS];
    if (threadIdx.x == 0) sniff_uids(ids_raw, s_uid);
    __syncthreads();

    const int w = blockIdx.x * (blockDim.x >> 5) + (threadIdx.x >> 5);
    const int lane = threadIdx.x & 31;
    const int TOTAL = B_USERS * M_DIM + B_USERS + M_DIM * M_DIM;  // 736
    if (w >= TOTAL) return;

    const float4* pa;
    const float4* pb;
    float* dst;
    if (w < B_USERS * M_DIM) {
        int b = w / M_DIM, m = w % M_DIM;
        pa = (const float4*)(users + (size_t)s_uid[b] * D_DIM);
        pb = (const float4*)(mems + m * D_DIM);
        dst = &g_UM[w];
    } else if (w < B_USERS * M_DIM + B_USERS) {
        int b = w - B_USERS * M_DIM;
        pa = (const float4*)(users + (size_t)s_uid[b] * D_DIM);
        pb = pa;
        dst = &g_u2[b];
    } else {
        int t = w - B_USERS * M_DIM - B_USERS;
        pa = (const float4*)(mems + (t / M_DIM) * D_DIM);
        pb = (const float4*)(mems + (t % M_DIM) * D_DIM);
        dst = &g_G[t];
    }
    float4 a = pa[lane], b = pb[lane];
    float s = a.x * b.x + a.y * b.y + a.z * b.z + a.w * b.w;
#pragma unroll
    for (int o = 16; o; o >>= 1) s += __shfl_xor_sync(0xffffffffu, s, o);
    if (lane == 0) *dst = s;
}

// ----------------------------------------------------------------------------
// Fused GEMM + epilogue: 148 persistent CTAs, 8 warps.
// ----------------------------------------------------------------------------
__global__ void __launch_bounds__(256, 1)
fused_kernel(const float* __restrict__ items,
             const float* __restrict__ users,
             const float* __restrict__ keyM,
             const float* __restrict__ mems,
             const void*  __restrict__ ids_raw,
             float* __restrict__ out, int N)
{
    extern __shared__ float smem[];
    float* Ws = smem;                         // [C_W][128] swizzled
    float* As = smem + C_W * 128;             // [CHUNK][128] swizzled
    float* Ls = As + CHUNK * 128;             // [CHUNK][LSTRIDE]

    __shared__ int s_uid[B_USERS];
    __shared__ float Gs[M_DIM * M_DIM];
    __shared__ float UMs[B_USERS * M_DIM];
    __shared__ float u2s[B_USERS];
    __shared__ float it2s[CHUNK];

    const int tid  = threadIdx.x;
    const int warp = tid >> 5;
    const int lane = tid & 31;
    const int g    = lane >> 2;
    const int tig  = lane & 3;

    if (tid == 0) sniff_uids(ids_raw, s_uid);
    for (int i = tid; i < M_DIM * M_DIM; i += 256) Gs[i] = g_G[i];
    for (int i = tid; i < B_USERS * M_DIM; i += 256) UMs[i] = g_UM[i];
    if (tid < B_USERS) u2s[tid] = g_u2[tid];
    __syncthreads();

    // Build W (tf32-rounded) into swizzled shared layout
    for (int idx = tid; idx < C_W * D_DIM; idx += 256) {
        int c = idx >> 7, d = idx & 127;
        float w = 0.f;
        if (c < B_USERS * 21) {
            int b = c / 21, j = c - b * 21;
            float u = users[(size_t)s_uid[b] * D_DIM + d];
            w = (j < M_DIM) ? u * keyM[d * M_DIM + j] : u;
        } else if (c < C_USE) {
            w = mems[(c - B_USERS * 21) * D_DIM + d];
        }
        Ws[c * 128 + swz_pos(d, c & 1)] = f2tf32f(w);
    }
    __syncthreads();

    // Per-thread mainloop pointers (float4 units, rows of 32 float4s)
    const float4* pA0 = (const float4*)As + g * 32;
    const float4* pA1 = pA0 + 8 * 32;
    const float4* pB[6];
#pragma unroll
    for (int j = 0; j < 6; j++) {
        int f = warp + 8 * j;
        if (f >= NFRAGS) f = 0;               // harmless duplicate, never dumped
        pB[j] = (const float4*)Ws + (f * 8 + g) * 32;
    }
    const int xb = g & 1;

    const float4* itemsv = (const float4*)items;

    for (int base = blockIdx.x * CHUNK; base < N; base += GRID * CHUNK) {
        // ---- stage A: 128 threads, thread (r,p) handles 16 k's of row r ----
        if (tid < 128) {
            int r = tid >> 3, p = tid & 7;
            int n = base + r;
            float4 v0, v1, v2, v3;
            if (n < N) {
                const float4* src = itemsv + (size_t)n * 32 + 4 * p;
                v0 = src[0]; v1 = src[1]; v2 = src[2]; v3 = src[3];
            } else {
                v0 = v1 = v2 = v3 = make_float4(0.f, 0.f, 0.f, 0.f);
            }
            // |item|^2 partial (raw fp32)
            float s = v0.x*v0.x + v0.y*v0.y + v0.z*v0.z + v0.w*v0.w
                    + v1.x*v1.x + v1.y*v1.y + v1.z*v1.z + v1.w*v1.w
                    + v2.x*v2.x + v2.y*v2.y + v2.z*v2.z + v2.w*v2.w
                    + v3.x*v3.x + v3.y*v3.y + v3.z*v3.z + v3.w*v3.w;
#pragma unroll
            for (int o = 4; o; o >>= 1)
                s += __shfl_down_sync(0xffffffffu, s, o, 8);
            if (p == 0) it2s[r] = s;

            // tf32 round
            v0.x=f2tf32f(v0.x); v0.y=f2tf32f(v0.y); v0.z=f2tf32f(v0.z); v0.w=f2tf32f(v0.w);
            v1.x=f2tf32f(v1.x); v1.y=f2tf32f(v1.y); v1.z=f2tf32f(v1.z); v1.w=f2tf32f(v1.w);
            v2.x=f2tf32f(v2.x); v2.y=f2tf32f(v2.y); v2.z=f2tf32f(v2.z); v2.w=f2tf32f(v2.w);
            v3.x=f2tf32f(v3.x); v3.y=f2tf32f(v3.y); v3.z=f2tf32f(v3.z); v3.w=f2tf32f(v3.w);

            // repack (4x4 transpose) and store 4 STS.128
            int rxb = r & 1, sp = (p >> 1) & 3, cb = 4 * (p ^ rxb);
            float4* dst = (float4*)(As + r * 128);
            dst[cb + (0 ^ sp)] = make_float4(v0.x, v1.x, v2.x, v3.x);
            dst[cb + (1 ^ sp)] = make_float4(v0.y, v1.y, v2.y, v3.y);
            dst[cb + (2 ^ sp)] = make_float4(v0.z, v1.z, v2.z, v3.z);
            dst[cb + (3 ^ sp)] = make_float4(v0.w, v1.w, v2.w, v3.w);
        }
        __syncthreads();

        // ---- mma mainloop: 8 k-pairs, LDS.128 operands ----
        float acc[6][4];
#pragma unroll
        for (int j = 0; j < 6; j++)
#pragma unroll
            for (int q = 0; q < 4; q++) acc[j][q] = 0.f;

#pragma unroll
        for (int p = 0; p < 8; p++) {
            const int pe = p ^ xb;
            const int o = 4 * pe + (tig ^ ((p >> 1) & 3));
            float4 a0 = pA0[o];
            float4 a1 = pA1[o];
            float4 b0 = pB[0][o], b1 = pB[1][o], b2 = pB[2][o];
            float4 b3 = pB[3][o], b4 = pB[4][o], b5 = pB[5][o];
            // kk = 2p  (k0 = 16p): a = {a0.x, a1.x, a0.y, a1.y}
            mma_tf32(acc[0], __float_as_uint(a0.x), __float_as_uint(a1.x),
                             __float_as_uint(a0.y), __float_as_uint(a1.y),
                             __float_as_uint(b0.x), __float_as_uint(b0.y));
            mma_tf32(acc[1], __float_as_uint(a0.x), __float_as_uint(a1.x),
                             __float_as_uint(a0.y), __float_as_uint(a1.y),
                             __float_as_uint(b1.x), __float_as_uint(b1.y));
            mma_tf32(acc[2], __float_as_uint(a0.x), __float_as_uint(a1.x),
                             __float_as_uint(a0.y), __float_as_uint(a1.y),
                             __float_as_uint(b2.x), __float_as_uint(b2.y));
            mma_tf32(acc[3], __float_as_uint(a0.x), __float_as_uint(a1.x),
                             __float_as_uint(a0.y), __float_as_uint(a1.y),
                             __float_as_uint(b3.x), __float_as_uint(b3.y));
            mma_tf32(acc[4], __float_as_uint(a0.x), __float_as_uint(a1.x),
                             __float_as_uint(a0.y), __float_as_uint(a1.y),
                             __float_as_uint(b4.x), __float_as_uint(b4.y));
            mma_tf32(acc[5], __float_as_uint(a0.x), __float_as_uint(a1.x),
                             __float_as_uint(a0.y), __float_as_uint(a1.y),
                             __float_as_uint(b5.x), __float_as_uint(b5.y));
            // kk = 2p+1 (k0 = 16p+8): a = {a0.z, a1.z, a0.w, a1.w}
            mma_tf32(acc[0], __float_as_uint(a0.z), __float_as_uint(a1.z),
                             __float_as_uint(a0.w), __float_as_uint(a1.w),
                             __float_as_uint(b0.z), __float_as_uint(b0.w));
            mma_tf32(acc[1], __float_as_uint(a0.z), __float_as_uint(a1.z),
                             __float_as_uint(a0.w), __float_as_uint(a1.w),
                             __float_as_uint(b1.z), __float_as_uint(b1.w));
            mma_tf32(acc[2], __float_as_uint(a0.z), __float_as_uint(a1.z),
                             __float_as_uint(a0.w), __float_as_uint(a1.w),
                             __float_as_uint(b2.z), __float_as_uint(b2.w));
            mma_tf32(acc[3], __float_as_uint(a0.z), __float_as_uint(a1.z),
                             __float_as_uint(a0.w), __float_as_uint(a1.w),
                             __float_as_uint(b3.z), __float_as_uint(b3.w));
            mma_tf32(acc[4], __float_as_uint(a0.z), __float_as_uint(a1.z),
                             __float_as_uint(a0.w), __float_as_uint(a1.w),
                             __float_as_uint(b4.z), __float_as_uint(b4.w));
            mma_tf32(acc[5], __float_as_uint(a0.z), __float_as_uint(a1.z),
                             __float_as_uint(a0.w), __float_as_uint(a1.w),
                             __float_as_uint(b5.z), __float_as_uint(b5.w));
        }

        // ---- dump acc to Ls (only real frags) ----
#pragma unroll
        for (int j = 0; j < 6; j++) {
            int f = warp + 8 * j;
            if (f < NFRAGS) {
                int col = f * 8 + 2 * tig;
                *(float2*)&Ls[g * LSTRIDE + col] =
                    make_float2(acc[j][0], acc[j][1]);
                *(float2*)&Ls[(g + 8) * LSTRIDE + col] =
                    make_float2(acc[j][2], acc[j][3]);
            }
        }
        __syncthreads();

        // ---- epilogue: thread (b = tid>>4, nl = tid&15) ----
        {
            const int b  = tid >> 4;
            const int nl = tid & 15;
            const int n  = base + nl;
            if (n < N) {
                const float* srow = &Ls[nl * LSTRIDE];
                const float* lb = srow + b * 21;

                float l[M_DIM];
#pragma unroll
                for (int j = 0; j < M_DIM; j++) l[j] = lb[j];
                float uit = lb[M_DIM];

                float mx = l[0];
#pragma unroll
                for (int j = 1; j < M_DIM; j++) mx = fmaxf(mx, l[j]);

                float2 e2[M_DIM / 2];
                float S = 0.f;
#pragma unroll
                for (int j = 0; j < M_DIM / 2; j++) {
                    float ea = __expf(l[2 * j] - mx);
                    float eb = __expf(l[2 * j + 1] - mx);
                    e2[j] = make_float2(ea, eb);
                    S += ea + eb;
                }

                float2 acc1 = make_float2(0.f, 0.f);
#pragma unroll
                for (int j = 0; j < M_DIM / 2; j++) {
                    float2 um = *(const float2*)&UMs[b * M_DIM + 2 * j];
                    float2 im = *(const float2*)&srow[B_USERS * 21 + 2 * j];
                    acc1 = ffma2(e2[j], make_float2(um.x - im.x, um.y - im.y), acc1);
                }
                float num1 = acc1.x + acc1.y;

                float Q = 0.f;
#pragma unroll
                for (int m2 = 0; m2 < M_DIM / 2; m2++) {
                    float2 qa = make_float2(0.f, 0.f);
                    float2 qb = make_float2(0.f, 0.f);
                    const float2* Gr0 = (const float2*)&Gs[(2 * m2) * M_DIM];
                    const float2* Gr1 = (const float2*)&Gs[(2 * m2 + 1) * M_DIM];
#pragma unroll
                    for (int j = 0; j < M_DIM / 2; j++) {
                        qa = ffma2(Gr0[j], e2[j], qa);
                        qb = ffma2(Gr1[j], e2[j], qb);
                    }
                    Q += e2[m2].x * (qa.x + qa.y) + e2[m2].y * (qb.x + qb.y);
                }

                float invS = 1.f / S;
                float s2 = u2s[b] + it2s[nl] - 2.f * uit
                         + 2.f * num1 * invS + Q * invS * invS;
                out[(size_t)b * N + n] = -sqrtf(fmaxf(s2, 0.f));
            }
        }
        __syncthreads();
    }
}

// ----------------------------------------------------------------------------
extern "C" void kernel_launch(void* const* d_in, const int* in_sizes, int n_in,
                              void* d_out, int out_size)
{
    const float* users = (const float*)d_in[0];
    const float* items = (const float*)d_in[1];
    const float* keyM  = (const float*)d_in[2];
    const float* mems  = (const float*)d_in[3];
    const void*  ids   = d_in[4];
    float* out = (float*)d_out;

    const int N = in_sizes[1] / D_DIM;

    const int smem_bytes = (C_W * 128 + CHUNK * 128 + CHUNK * LSTRIDE) * 4;
    cudaFuncSetAttribute(fused_kernel,
                         cudaFuncAttributeMaxDynamicSharedMemorySize, smem_bytes);

    pre2_kernel<<<92, 256>>>(users, mems, ids);
    fused_kernel<<<GRID, 256, smem_bytes>>>(items, users, keyM, mems, ids, out, N);
}